// round 3
// baseline (speedup 1.0000x reference)
#include <cuda_runtime.h>
#include <math.h>
#include <stdint.h>

#define L 4
#define NN 40000
#define D 128
#define KD 16
#define NE 320000
#define MROWS (L*NN)                 // 160000
#define SLICE ((size_t)NN*(size_t)D) // 5,120,000
#define VST 132                      // LN staging row stride (16B-aligned rows)

// ---------------- scratch (static device memory; no allocations) ----------------
static __device__ float g_S1[(size_t)L*NN*D];   // spmm(vals, x)      [L,N,D]
static __device__ float g_S2[(size_t)L*NN*D];   // spmm(vals, S1)     [L,N,D]
static __device__ float g_h [(size_t)L*NN*D];   // sage_out+attn_out  [L,N,D]
static __device__ float g_w [MROWS];            // retention weights  [L*N]
static __device__ int   g_rowptr[NN+1];
static __device__ int   g_cnt[NN];
static __device__ int   g_cur[NN];
static __device__ int   g_ecol[NE];
static __device__ float g_eval[NE];

// ---------------- CSR build ----------------
__global__ void k_zero_counts() {
    int i = blockIdx.x*blockDim.x + threadIdx.x;
    if (i < NN) { g_cnt[i] = 0; g_cur[i] = 0; }
}

__global__ void k_hist(const int* __restrict__ rows) {
    int e = blockIdx.x*blockDim.x + threadIdx.x;
    if (e < NE) atomicAdd(&g_cnt[rows[e]], 1);
}

__global__ void k_scan() {
    __shared__ int sh[1024];
    int tid = threadIdx.x;
    int run = 0;
    const int TILES = (NN + 1023) / 1024;
    for (int t = 0; t < TILES; ++t) {
        int i = t*1024 + tid;
        int v = (i < NN) ? g_cnt[i] : 0;
        sh[tid] = v;
        __syncthreads();
        for (int off = 1; off < 1024; off <<= 1) {
            int add = (tid >= off) ? sh[tid - off] : 0;
            __syncthreads();
            sh[tid] += add;
            __syncthreads();
        }
        if (i < NN) g_rowptr[i] = run + sh[tid] - v;   // exclusive
        run += sh[1023];
        __syncthreads();
    }
    if (tid == 0) g_rowptr[NN] = run;
}

__global__ void k_scatter(const int* __restrict__ rows, const int* __restrict__ cols,
                          const float* __restrict__ vals) {
    int e = blockIdx.x*blockDim.x + threadIdx.x;
    if (e < NE) {
        int r = rows[e];
        int p = atomicAdd(&g_cur[r], 1);
        int idx = g_rowptr[r] + p;
        g_ecol[idx] = cols[e];
        g_eval[idx] = vals[e];
    }
}

// ---------------- SPMM: out[l,r,:] = sum_e val * in[l,col,:] ----------------
// stage 0: in = x (arg), out = g_S1.  stage 1: in = g_S1, out = g_S2.
// (Device globals must only be referenced from device code — host-side
//  references resolve to the host shadow and silently write host memory on GB300/ATS.)
__global__ __launch_bounds__(128) void k_spmm(const float* __restrict__ x, int stage) {
    const float* __restrict__ in  = (stage == 0) ? x    : (const float*)g_S1;
    float*       __restrict__ out = (stage == 0) ? g_S1 : g_S2;
    int r = blockIdx.x;
    int d = threadIdx.x;
    int s  = g_rowptr[r];
    int e2 = g_rowptr[r+1];
    float a0 = 0.f, a1 = 0.f, a2 = 0.f, a3 = 0.f;
    for (int i = s; i < e2; ++i) {
        int   c = g_ecol[i];
        float v = g_eval[i];
        const float* p = in + (size_t)c*D + d;
        a0 += v * p[0];
        a1 += v * p[SLICE];
        a2 += v * p[2*SLICE];
        a3 += v * p[3*SLICE];
    }
    size_t o = (size_t)r*D + d;
    out[o]           = a0;
    out[o +   SLICE] = a1;
    out[o + 2*SLICE] = a2;
    out[o + 3*SLICE] = a3;
}

// ---------------- retention weights ----------------
// w[m] = (1/16) * sum_{t in {x, 0.5*S1, 0.25*S2}} sum_k (z_t . Kw_k)(z_t . Qw_k)
__global__ __launch_bounds__(256) void k_weights(const float* __restrict__ x,
                                                 const float* __restrict__ keyW,
                                                 const float* __restrict__ qryW) {
    __shared__ __align__(16) float Kw[D*KD];
    __shared__ __align__(16) float Qw[D*KD];
    __shared__ float Zs[32*129];
    __shared__ float wsum[256];
    int tid  = threadIdx.x;
    for (int i = tid; i < D*KD; i += 256) { Kw[i] = keyW[i]; Qw[i] = qryW[i]; }
    int row  = tid & 127;
    int half = tid >> 7;
    size_t m0 = (size_t)blockIdx.x * 128;
    int kb = half * 8;
    float wacc = 0.f;
    #pragma unroll
    for (int t = 0; t < 3; ++t) {
        const float* src = (t == 0) ? x : (t == 1) ? (const float*)g_S1 : (const float*)g_S2;
        float sc = (t == 0) ? 1.f : (t == 1) ? 0.5f : 0.25f;
        float aK[8] = {0,0,0,0,0,0,0,0};
        float aQ[8] = {0,0,0,0,0,0,0,0};
        for (int dc = 0; dc < D; dc += 32) {
            __syncthreads();
            for (int i = tid; i < 128*32; i += 256) {
                int dd = i & 31, rr = i >> 5;
                Zs[dd*129 + rr] = sc * src[(m0 + rr)*(size_t)D + dc + dd];
            }
            __syncthreads();
            #pragma unroll
            for (int dd = 0; dd < 32; ++dd) {
                float zv = Zs[dd*129 + row];
                const float* kp = &Kw[(dc + dd)*KD + kb];
                const float* qp = &Qw[(dc + dd)*KD + kb];
                float4 k0 = *(const float4*)kp, k1 = *(const float4*)(kp + 4);
                float4 q0 = *(const float4*)qp, q1 = *(const float4*)(qp + 4);
                aK[0] += zv*k0.x; aK[1] += zv*k0.y; aK[2] += zv*k0.z; aK[3] += zv*k0.w;
                aK[4] += zv*k1.x; aK[5] += zv*k1.y; aK[6] += zv*k1.z; aK[7] += zv*k1.w;
                aQ[0] += zv*q0.x; aQ[1] += zv*q0.y; aQ[2] += zv*q0.z; aQ[3] += zv*q0.w;
                aQ[4] += zv*q1.x; aQ[5] += zv*q1.y; aQ[6] += zv*q1.z; aQ[7] += zv*q1.w;
            }
        }
        float p = 0.f;
        #pragma unroll
        for (int k = 0; k < 8; ++k) p += aK[k]*aQ[k];
        wacc += p;
    }
    wsum[tid] = wacc;
    __syncthreads();
    if (half == 0) g_w[m0 + row] = (wacc + wsum[tid + 128]) * (1.f/16.f);
}

// ---------------- fused GEMM helpers ----------------
// One stage: acc1 += A@B1 (optional), acc2 += A@(vscale*B2). BM=64, BN=128, BK=16.
template<bool HASB1>
__device__ __forceinline__ void gemm_stage(const float* __restrict__ A,
                                           const float* __restrict__ B1,
                                           const float* __restrict__ B2,
                                           float vscale,
                                           float* As, float* Bs1, float* Bs2,
                                           size_t m0, int tid, int tx, int ty,
                                           float acc1[4][8], float acc2[4][8]) {
    for (int kc = 0; kc < D; kc += 16) {
        __syncthreads();
        #pragma unroll
        for (int i = tid; i < 64*16; i += 256) {
            int r = i >> 4, kk = i & 15;
            As[r*17 + kk] = A[(m0 + r)*(size_t)D + kc + kk];
        }
        #pragma unroll
        for (int i = tid; i < 16*128; i += 256) {
            int kk = i >> 7, c = i & 127;
            if (HASB1) Bs1[i] = B1[(size_t)(kc + kk)*D + c];
            Bs2[i] = vscale * B2[(size_t)(kc + kk)*D + c];
        }
        __syncthreads();
        #pragma unroll
        for (int kk = 0; kk < 16; ++kk) {
            float a[4];
            #pragma unroll
            for (int r = 0; r < 4; ++r) a[r] = As[(ty*4 + r)*17 + kk];
            float b2[8];
            {
                float4 u = *(const float4*)&Bs2[kk*128 + tx*8];
                float4 v = *(const float4*)&Bs2[kk*128 + tx*8 + 4];
                b2[0]=u.x; b2[1]=u.y; b2[2]=u.z; b2[3]=u.w;
                b2[4]=v.x; b2[5]=v.y; b2[6]=v.z; b2[7]=v.w;
            }
            if (HASB1) {
                float b1[8];
                float4 u = *(const float4*)&Bs1[kk*128 + tx*8];
                float4 v = *(const float4*)&Bs1[kk*128 + tx*8 + 4];
                b1[0]=u.x; b1[1]=u.y; b1[2]=u.z; b1[3]=u.w;
                b1[4]=v.x; b1[5]=v.y; b1[6]=v.z; b1[7]=v.w;
                #pragma unroll
                for (int r = 0; r < 4; ++r)
                    #pragma unroll
                    for (int c = 0; c < 8; ++c) acc1[r][c] += a[r]*b1[c];
            }
            #pragma unroll
            for (int r = 0; r < 4; ++r)
                #pragma unroll
                for (int c = 0; c < 8; ++c) acc2[r][c] += a[r]*b2[c];
        }
    }
}

__device__ __forceinline__ float silu_f(float v) { return v / (1.f + expf(-v)); }

// G1: h = silu(x@sageW + S1@aggW + sageB) + LN((x+0.5S1+0.25S2)@valW * w)
__global__ __launch_bounds__(256) void k_g1(const float* __restrict__ x,
                                            const float* __restrict__ sageW,
                                            const float* __restrict__ sageB,
                                            const float* __restrict__ aggW,
                                            const float* __restrict__ valW,
                                            const float* __restrict__ lnG,
                                            const float* __restrict__ lnB) {
    __shared__ __align__(16) float sm[64*VST];   // GEMM tiles, then Vs staging
    __shared__ float w_s[64];
    __shared__ float mu_s[64], rs_s[64];
    float* As  = sm;                 // 64*17  = 1088
    float* Bs1 = sm + 1088;          // 16*128 = 2048
    float* Bs2 = sm + 1088 + 2048;   // 2048
    int tid = threadIdx.x;
    int tx = tid & 15;   // 8-col group
    int ty = tid >> 4;   // 4-row group
    size_t m0 = (size_t)blockIdx.x * 64;
    if (tid < 64) w_s[tid] = g_w[m0 + tid];

    float acc1[4][8]; float acc2[4][8];
    #pragma unroll
    for (int r = 0; r < 4; ++r)
        #pragma unroll
        for (int c = 0; c < 8; ++c) { acc1[r][c] = 0.f; acc2[r][c] = 0.f; }

    gemm_stage<true >(x,    sageW, valW, 1.f,   As, Bs1, Bs2, m0, tid, tx, ty, acc1, acc2);
    gemm_stage<true >(g_S1, aggW,  valW, 0.5f,  As, Bs1, Bs2, m0, tid, tx, ty, acc1, acc2);
    gemm_stage<false>(g_S2, 0,     valW, 0.25f, As, Bs1, Bs2, m0, tid, tx, ty, acc1, acc2);

    // sage = silu(acc1 + b)  (kept in registers, acc1 reused)
    float bb[8];
    {
        float4 u = *(const float4*)&sageB[tx*8];
        float4 v = *(const float4*)&sageB[tx*8 + 4];
        bb[0]=u.x; bb[1]=u.y; bb[2]=u.z; bb[3]=u.w; bb[4]=v.x; bb[5]=v.y; bb[6]=v.z; bb[7]=v.w;
    }
    #pragma unroll
    for (int r = 0; r < 4; ++r)
        #pragma unroll
        for (int c = 0; c < 8; ++c) acc1[r][c] = silu_f(acc1[r][c] + bb[c]);

    // stage vout*w into shared for row LN
    __syncthreads();
    float* Vs = sm; // [64][VST]
    #pragma unroll
    for (int r = 0; r < 4; ++r) {
        int row = ty*4 + r;
        float wv = w_s[row];
        #pragma unroll
        for (int c = 0; c < 8; ++c)
            Vs[row*VST + tx*8 + c] = acc2[r][c] * wv;
    }
    __syncthreads();
    int wid = tid >> 5, lane = tid & 31;
    for (int r = wid; r < 64; r += 8) {
        float s = 0.f, q = 0.f;
        #pragma unroll
        for (int c = lane; c < 128; c += 32) { float v = Vs[r*VST + c]; s += v; q += v*v; }
        #pragma unroll
        for (int o = 16; o > 0; o >>= 1) {
            s += __shfl_down_sync(0xffffffffu, s, o);
            q += __shfl_down_sync(0xffffffffu, q, o);
        }
        if (lane == 0) {
            float mu = s * (1.f/128.f);
            float var = q * (1.f/128.f) - mu*mu;
            mu_s[r] = mu;
            rs_s[r] = rsqrtf(var + 1e-5f);
        }
    }
    __syncthreads();
    float g8[8], b8[8];
    {
        float4 u = *(const float4*)&lnG[tx*8]; float4 v = *(const float4*)&lnG[tx*8+4];
        g8[0]=u.x; g8[1]=u.y; g8[2]=u.z; g8[3]=u.w; g8[4]=v.x; g8[5]=v.y; g8[6]=v.z; g8[7]=v.w;
        u = *(const float4*)&lnB[tx*8]; v = *(const float4*)&lnB[tx*8+4];
        b8[0]=u.x; b8[1]=u.y; b8[2]=u.z; b8[3]=u.w; b8[4]=v.x; b8[5]=v.y; b8[6]=v.z; b8[7]=v.w;
    }
    #pragma unroll
    for (int r = 0; r < 4; ++r) {
        int row = ty*4 + r;
        float mu = mu_s[row], rs = rs_s[row];
        float4 va = *(const float4*)&Vs[row*VST + tx*8];
        float4 vb = *(const float4*)&Vs[row*VST + tx*8 + 4];
        float v8[8] = {va.x, va.y, va.z, va.w, vb.x, vb.y, vb.z, vb.w};
        float o8[8];
        #pragma unroll
        for (int c = 0; c < 8; ++c)
            o8[c] = acc1[r][c] + (v8[c] - mu) * rs * g8[c] + b8[c];
        float* dst = &g_h[(m0 + row)*(size_t)D + tx*8];
        *(float4*)dst       = make_float4(o8[0], o8[1], o8[2], o8[3]);
        *(float4*)(dst + 4) = make_float4(o8[4], o8[5], o8[6], o8[7]);
    }
}

// G2: out = LN(silu(h@linW + linB))
__global__ __launch_bounds__(256) void k_g2(const float* __restrict__ linW,
                                            const float* __restrict__ linB,
                                            const float* __restrict__ lnG,
                                            const float* __restrict__ lnB,
                                            float* __restrict__ out) {
    __shared__ __align__(16) float sm[64*VST];
    __shared__ float mu_s[64], rs_s[64];
    float* As  = sm;
    float* Bs1 = sm + 1088;   // unused
    float* Bs2 = sm + 1088 + 2048;
    int tid = threadIdx.x;
    int tx = tid & 15;
    int ty = tid >> 4;
    size_t m0 = (size_t)blockIdx.x * 64;

    float acc1[4][8]; float acc2[4][8];
    #pragma unroll
    for (int r = 0; r < 4; ++r)
        #pragma unroll
        for (int c = 0; c < 8; ++c) { acc1[r][c] = 0.f; acc2[r][c] = 0.f; }

    gemm_stage<false>(g_h, 0, linW, 1.f, As, Bs1, Bs2, m0, tid, tx, ty, acc1, acc2);

    float bb[8];
    {
        float4 u = *(const float4*)&linB[tx*8];
        float4 v = *(const float4*)&linB[tx*8 + 4];
        bb[0]=u.x; bb[1]=u.y; bb[2]=u.z; bb[3]=u.w; bb[4]=v.x; bb[5]=v.y; bb[6]=v.z; bb[7]=v.w;
    }
    __syncthreads();
    float* Ys = sm;
    #pragma unroll
    for (int r = 0; r < 4; ++r) {
        int row = ty*4 + r;
        #pragma unroll
        for (int c = 0; c < 8; ++c)
            Ys[row*VST + tx*8 + c] = silu_f(acc2[r][c] + bb[c]);
    }
    __syncthreads();
    int wid = tid >> 5, lane = tid & 31;
    for (int r = wid; r < 64; r += 8) {
        float s = 0.f, q = 0.f;
        #pragma unroll
        for (int c = lane; c < 128; c += 32) { float v = Ys[r*VST + c]; s += v; q += v*v; }
        #pragma unroll
        for (int o = 16; o > 0; o >>= 1) {
            s += __shfl_down_sync(0xffffffffu, s, o);
            q += __shfl_down_sync(0xffffffffu, q, o);
        }
        if (lane == 0) {
            float mu = s * (1.f/128.f);
            float var = q * (1.f/128.f) - mu*mu;
            mu_s[r] = mu;
            rs_s[r] = rsqrtf(var + 1e-5f);
        }
    }
    __syncthreads();
    float g8[8], b8[8];
    {
        float4 u = *(const float4*)&lnG[tx*8]; float4 v = *(const float4*)&lnG[tx*8+4];
        g8[0]=u.x; g8[1]=u.y; g8[2]=u.z; g8[3]=u.w; g8[4]=v.x; g8[5]=v.y; g8[6]=v.z; g8[7]=v.w;
        u = *(const float4*)&lnB[tx*8]; v = *(const float4*)&lnB[tx*8+4];
        b8[0]=u.x; b8[1]=u.y; b8[2]=u.z; b8[3]=u.w; b8[4]=v.x; b8[5]=v.y; b8[6]=v.z; b8[7]=v.w;
    }
    #pragma unroll
    for (int r = 0; r < 4; ++r) {
        int row = ty*4 + r;
        float mu = mu_s[row], rs = rs_s[row];
        float4 va = *(const float4*)&Ys[row*VST + tx*8];
        float4 vb = *(const float4*)&Ys[row*VST + tx*8 + 4];
        float v8[8] = {va.x, va.y, va.z, va.w, vb.x, vb.y, vb.z, vb.w};
        float o8[8];
        #pragma unroll
        for (int c = 0; c < 8; ++c)
            o8[c] = (v8[c] - mu) * rs * g8[c] + b8[c];
        float* dst = &out[(m0 + row)*(size_t)D + tx*8];
        *(float4*)dst       = make_float4(o8[0], o8[1], o8[2], o8[3]);
        *(float4*)(dst + 4) = make_float4(o8[4], o8[5], o8[6], o8[7]);
    }
}

// ---------------- launch ----------------
extern "C" void kernel_launch(void* const* d_in, const int* in_sizes, int n_in,
                              void* d_out, int out_size) {
    const float* x         = (const float*)d_in[0];
    const int*   edge_rows = (const int*)  d_in[1];
    const int*   edge_cols = (const int*)  d_in[2];
    const float* edge_vals = (const float*)d_in[3];
    const float* sage_W    = (const float*)d_in[4];
    const float* sage_b    = (const float*)d_in[5];
    const float* sage_aggW = (const float*)d_in[6];
    const float* key_W     = (const float*)d_in[7];
    const float* query_W   = (const float*)d_in[8];
    const float* value_W   = (const float*)d_in[9];
    const float* attn_ln_g = (const float*)d_in[10];
    const float* attn_ln_b = (const float*)d_in[11];
    const float* lin_W     = (const float*)d_in[12];
    const float* lin_b     = (const float*)d_in[13];
    const float* ln_g      = (const float*)d_in[14];
    const float* ln_b      = (const float*)d_in[15];
    float* out = (float*)d_out;

    // CSR build
    k_zero_counts<<<(NN + 255)/256, 256>>>();
    k_hist<<<(NE + 255)/256, 256>>>(edge_rows);
    k_scan<<<1, 1024>>>();
    k_scatter<<<(NE + 255)/256, 256>>>(edge_rows, edge_cols, edge_vals);

    // S1 = spmm(x), S2 = spmm(S1)  (buffers selected inside the kernel)
    k_spmm<<<NN, 128>>>(x, 0);
    k_spmm<<<NN, 128>>>(x, 1);

    // retention weights
    k_weights<<<MROWS/128, 256>>>(x, key_W, query_W);

    // fused sage + value/attn  ->  h
    k_g1<<<MROWS/64, 256>>>(x, sage_W, sage_b, sage_aggW, value_W, attn_ln_g, attn_ln_b);

    // final lin + silu + LN -> out
    k_g2<<<MROWS/64, 256>>>(lin_W, lin_b, ln_g, ln_b, out);
}

// round 4
// speedup vs baseline: 1.3550x; 1.3550x over previous
#include <cuda_runtime.h>
#include <math.h>
#include <stdint.h>

#define L 4
#define NN 40000
#define D 128
#define KD 16
#define NE 320000
#define MROWS (L*NN)                 // 160000
#define SLICE ((size_t)NN*(size_t)D) // 5,120,000
#define VST 132                      // LN staging row stride (16B-aligned rows)

typedef unsigned long long ull;

// ---------------- packed fp32x2 helpers (sm_100+) ----------------
__device__ __forceinline__ ull pack2(float lo, float hi) {
    ull r; asm("mov.b64 %0, {%1,%2};" : "=l"(r) : "f"(lo), "f"(hi)); return r;
}
__device__ __forceinline__ void fma2(ull& d, ull a, ull b) {
    asm("fma.rn.f32x2 %0, %1, %2, %0;" : "+l"(d) : "l"(a), "l"(b));
}
__device__ __forceinline__ float2 unp2(ull v) {
    float2 r; asm("mov.b64 {%0,%1}, %2;" : "=f"(r.x), "=f"(r.y) : "l"(v)); return r;
}

// ---------------- scratch (static device memory; no allocations) ----------------
static __device__ float g_S1[(size_t)L*NN*D];   // spmm(vals, x)          [L,N,D]
static __device__ float g_S2[(size_t)L*NN*D];   // spmm(vals, S1)         [L,N,D]
static __device__ float g_X [(size_t)L*NN*D];   // x + 0.5 S1 + 0.25 S2   [L,N,D]
static __device__ float g_h [(size_t)L*NN*D];   // sage_out+attn_out      [L,N,D]
static __device__ float g_w [MROWS];            // retention weights      [L*N]
static __device__ int   g_rowptr[NN+1];
static __device__ int   g_cnt[NN];
static __device__ int   g_cur[NN];
static __device__ int   g_ecol[NE];
static __device__ float g_eval[NE];

// ---------------- CSR build ----------------
__global__ void k_zero_counts() {
    int i = blockIdx.x*blockDim.x + threadIdx.x;
    if (i < NN) { g_cnt[i] = 0; g_cur[i] = 0; }
}

__global__ void k_hist(const int* __restrict__ rows) {
    int e = blockIdx.x*blockDim.x + threadIdx.x;
    if (e < NE) atomicAdd(&g_cnt[rows[e]], 1);
}

__global__ void k_scan() {
    __shared__ int sh[1024];
    int tid = threadIdx.x;
    int run = 0;
    const int TILES = (NN + 1023) / 1024;
    for (int t = 0; t < TILES; ++t) {
        int i = t*1024 + tid;
        int v = (i < NN) ? g_cnt[i] : 0;
        sh[tid] = v;
        __syncthreads();
        for (int off = 1; off < 1024; off <<= 1) {
            int add = (tid >= off) ? sh[tid - off] : 0;
            __syncthreads();
            sh[tid] += add;
            __syncthreads();
        }
        if (i < NN) g_rowptr[i] = run + sh[tid] - v;   // exclusive
        run += sh[1023];
        __syncthreads();
    }
    if (tid == 0) g_rowptr[NN] = run;
}

__global__ void k_scatter(const int* __restrict__ rows, const int* __restrict__ cols,
                          const float* __restrict__ vals) {
    int e = blockIdx.x*blockDim.x + threadIdx.x;
    if (e < NE) {
        int r = rows[e];
        int p = atomicAdd(&g_cur[r], 1);
        int idx = g_rowptr[r] + p;
        g_ecol[idx] = cols[e];
        g_eval[idx] = vals[e];
    }
}

// ---------------- SPMM: out[l,r,:] = sum_e val * in[l,col,:] ----------------
// stage 0: in = x,    out = g_S1.
// stage 1: in = g_S1, out = g_S2; also writes g_X = x + 0.5*S1 + 0.25*S2.
__global__ __launch_bounds__(128) void k_spmm(const float* __restrict__ x, int stage) {
    const float* __restrict__ in  = (stage == 0) ? x    : (const float*)g_S1;
    float*       __restrict__ out = (stage == 0) ? g_S1 : g_S2;
    int r = blockIdx.x;
    int d = threadIdx.x;
    int s  = g_rowptr[r];
    int e2 = g_rowptr[r+1];
    float a0 = 0.f, a1 = 0.f, a2 = 0.f, a3 = 0.f;
    for (int i = s; i < e2; ++i) {
        int   c = g_ecol[i];
        float v = g_eval[i];
        const float* p = in + (size_t)c*D + d;
        a0 += v * p[0];
        a1 += v * p[SLICE];
        a2 += v * p[2*SLICE];
        a3 += v * p[3*SLICE];
    }
    size_t o = (size_t)r*D + d;
    out[o]           = a0;
    out[o +   SLICE] = a1;
    out[o + 2*SLICE] = a2;
    out[o + 3*SLICE] = a3;
    if (stage == 1) {
        // in == g_S1 here; a* hold S2 values
        g_X[o]           = x[o]           + 0.5f*in[o]           + 0.25f*a0;
        g_X[o+  SLICE]   = x[o+  SLICE]   + 0.5f*in[o+  SLICE]   + 0.25f*a1;
        g_X[o+2*SLICE]   = x[o+2*SLICE]   + 0.5f*in[o+2*SLICE]   + 0.25f*a2;
        g_X[o+3*SLICE]   = x[o+3*SLICE]   + 0.5f*in[o+3*SLICE]   + 0.25f*a3;
    }
}

// ---------------- retention weights ----------------
// w[m] = (1/16) * sum_{t in {x, 0.5*S1, 0.25*S2}} sum_k (z_t . Kw_k)(z_t . Qw_k)
__global__ __launch_bounds__(256) void k_weights(const float* __restrict__ x,
                                                 const float* __restrict__ keyW,
                                                 const float* __restrict__ qryW) {
    __shared__ __align__(16) float Kw[D*KD];
    __shared__ __align__(16) float Qw[D*KD];
    __shared__ float Zs[32*129];
    __shared__ float wsum[256];
    int tid  = threadIdx.x;
    for (int i = tid; i < D*KD; i += 256) { Kw[i] = keyW[i]; Qw[i] = qryW[i]; }
    int row  = tid & 127;
    int half = tid >> 7;
    size_t m0 = (size_t)blockIdx.x * 128;
    int kb = half * 8;
    float wacc = 0.f;
    #pragma unroll
    for (int t = 0; t < 3; ++t) {
        const float* src = (t == 0) ? x : (t == 1) ? (const float*)g_S1 : (const float*)g_S2;
        float sc = (t == 0) ? 1.f : (t == 1) ? 0.5f : 0.25f;
        ull aK[4] = {0,0,0,0};
        ull aQ[4] = {0,0,0,0};
        for (int dc = 0; dc < D; dc += 32) {
            __syncthreads();
            for (int i = tid; i < 128*32; i += 256) {
                int dd = i & 31, rr = i >> 5;
                Zs[dd*129 + rr] = sc * src[(m0 + rr)*(size_t)D + dc + dd];
            }
            __syncthreads();
            #pragma unroll
            for (int dd = 0; dd < 32; ++dd) {
                float zv = Zs[dd*129 + row];
                ull zp = pack2(zv, zv);
                const ulonglong2* kp = (const ulonglong2*)&Kw[(dc + dd)*KD + kb];
                const ulonglong2* qp = (const ulonglong2*)&Qw[(dc + dd)*KD + kb];
                ulonglong2 k0 = kp[0], k1 = kp[1];
                ulonglong2 q0 = qp[0], q1 = qp[1];
                fma2(aK[0], zp, k0.x); fma2(aK[1], zp, k0.y);
                fma2(aK[2], zp, k1.x); fma2(aK[3], zp, k1.y);
                fma2(aQ[0], zp, q0.x); fma2(aQ[1], zp, q0.y);
                fma2(aQ[2], zp, q1.x); fma2(aQ[3], zp, q1.y);
            }
        }
        float p = 0.f;
        #pragma unroll
        for (int k = 0; k < 4; ++k) {
            float2 fk = unp2(aK[k]), fq = unp2(aQ[k]);
            p += fk.x*fq.x + fk.y*fq.y;
        }
        wacc += p;
    }
    wsum[tid] = wacc;
    __syncthreads();
    if (half == 0) g_w[m0 + row] = (wacc + wsum[tid + 128]) * (1.f/16.f);
}

// ---------------- single-GEMM tile pass: acc += A[m0:m0+64, :] @ B ----------------
// BM=64, BN=128, BK=16, 256 threads, per-thread 4 rows x 4 col-pairs, packed f32x2.
// As padded to 20-float row stride (float4-aligned rows, conflict-light).
__device__ __forceinline__ void gemm_one(const float* __restrict__ A,
                                         const float* __restrict__ B,
                                         float* As, float* Bs,
                                         size_t m0, int tid, int tx, int ty,
                                         ull acc[4][4]) {
    const float4* A4 = (const float4*)A;
    float4* As4 = (float4*)As;
    float4* Bs4 = (float4*)Bs;
    for (int kc = 0; kc < D; kc += 16) {
        __syncthreads();
        {   // As: 64 rows x 16 k (stride 20): 256 float4 stores
            int r = tid >> 2, q = tid & 3;
            As4[r*5 + q] = A4[(m0 + r)*(D/4) + (kc >> 2) + q];
            // Bs: 16 rows x 128 cols = 512 float4
            const float4* Bg = (const float4*)(B + (size_t)kc*D);
            Bs4[tid]       = Bg[tid];
            Bs4[tid + 256] = Bg[tid + 256];
        }
        __syncthreads();
        #pragma unroll
        for (int kk = 0; kk < 16; ++kk) {
            ull ap[4];
            #pragma unroll
            for (int r = 0; r < 4; ++r) {
                float av = As[(ty*4 + r)*20 + kk];
                ap[r] = pack2(av, av);
            }
            ulonglong2 b01 = *(const ulonglong2*)&Bs[kk*128 + tx*8];
            ulonglong2 b23 = *(const ulonglong2*)&Bs[kk*128 + tx*8 + 4];
            #pragma unroll
            for (int r = 0; r < 4; ++r) {
                fma2(acc[r][0], ap[r], b01.x);
                fma2(acc[r][1], ap[r], b01.y);
                fma2(acc[r][2], ap[r], b23.x);
                fma2(acc[r][3], ap[r], b23.y);
            }
        }
    }
}

__device__ __forceinline__ float silu_f(float v) { return v / (1.f + expf(-v)); }

// G1: h = silu(x@sageW + S1@aggW + sageB) + LN(Xacc@valW * w)
__global__ __launch_bounds__(256) void k_g1(const float* __restrict__ x,
                                            const float* __restrict__ sageW,
                                            const float* __restrict__ sageB,
                                            const float* __restrict__ aggW,
                                            const float* __restrict__ valW,
                                            const float* __restrict__ lnG,
                                            const float* __restrict__ lnB) {
    __shared__ __align__(16) float sm[64*VST];   // GEMM tiles (3328), then Vs staging
    __shared__ float w_s[64];
    __shared__ float mu_s[64], rs_s[64];
    float* As = sm;           // 64*20 = 1280
    float* Bs = sm + 1280;    // 16*128 = 2048
    int tid = threadIdx.x;
    int tx = tid & 15;   // 8-col group
    int ty = tid >> 4;   // 4-row group
    size_t m0 = (size_t)blockIdx.x * 64;
    if (tid < 64) w_s[tid] = g_w[m0 + tid];

    ull acc1[4][4], acc2[4][4];
    #pragma unroll
    for (int r = 0; r < 4; ++r)
        #pragma unroll
        for (int p = 0; p < 4; ++p) { acc1[r][p] = 0ull; acc2[r][p] = 0ull; }

    gemm_one(x,    sageW, As, Bs, m0, tid, tx, ty, acc1);
    gemm_one(g_S1, aggW,  As, Bs, m0, tid, tx, ty, acc1);
    gemm_one(g_X,  valW,  As, Bs, m0, tid, tx, ty, acc2);

    // unpack accumulators
    float a1[4][8], a2[4][8];
    #pragma unroll
    for (int r = 0; r < 4; ++r)
        #pragma unroll
        for (int p = 0; p < 4; ++p) {
            float2 f1 = unp2(acc1[r][p]);
            float2 f2 = unp2(acc2[r][p]);
            a1[r][2*p] = f1.x; a1[r][2*p+1] = f1.y;
            a2[r][2*p] = f2.x; a2[r][2*p+1] = f2.y;
        }

    // sage = silu(a1 + b)
    float bb[8];
    {
        float4 u = *(const float4*)&sageB[tx*8];
        float4 v = *(const float4*)&sageB[tx*8 + 4];
        bb[0]=u.x; bb[1]=u.y; bb[2]=u.z; bb[3]=u.w; bb[4]=v.x; bb[5]=v.y; bb[6]=v.z; bb[7]=v.w;
    }
    #pragma unroll
    for (int r = 0; r < 4; ++r)
        #pragma unroll
        for (int c = 0; c < 8; ++c) a1[r][c] = silu_f(a1[r][c] + bb[c]);

    // stage vout*w into shared for row LN
    __syncthreads();
    float* Vs = sm; // [64][VST]
    #pragma unroll
    for (int r = 0; r < 4; ++r) {
        int row = ty*4 + r;
        float wv = w_s[row];
        #pragma unroll
        for (int c = 0; c < 8; ++c)
            Vs[row*VST + tx*8 + c] = a2[r][c] * wv;
    }
    __syncthreads();
    int wid = tid >> 5, lane = tid & 31;
    for (int r = wid; r < 64; r += 8) {
        float s = 0.f, q = 0.f;
        #pragma unroll
        for (int c = lane; c < 128; c += 32) { float v = Vs[r*VST + c]; s += v; q += v*v; }
        #pragma unroll
        for (int o = 16; o > 0; o >>= 1) {
            s += __shfl_down_sync(0xffffffffu, s, o);
            q += __shfl_down_sync(0xffffffffu, q, o);
        }
        if (lane == 0) {
            float mu = s * (1.f/128.f);
            float var = q * (1.f/128.f) - mu*mu;
            mu_s[r] = mu;
            rs_s[r] = rsqrtf(var + 1e-5f);
        }
    }
    __syncthreads();
    float g8[8], b8[8];
    {
        float4 u = *(const float4*)&lnG[tx*8]; float4 v = *(const float4*)&lnG[tx*8+4];
        g8[0]=u.x; g8[1]=u.y; g8[2]=u.z; g8[3]=u.w; g8[4]=v.x; g8[5]=v.y; g8[6]=v.z; g8[7]=v.w;
        u = *(const float4*)&lnB[tx*8]; v = *(const float4*)&lnB[tx*8+4];
        b8[0]=u.x; b8[1]=u.y; b8[2]=u.z; b8[3]=u.w; b8[4]=v.x; b8[5]=v.y; b8[6]=v.z; b8[7]=v.w;
    }
    #pragma unroll
    for (int r = 0; r < 4; ++r) {
        int row = ty*4 + r;
        float mu = mu_s[row], rs = rs_s[row];
        float4 va = *(const float4*)&Vs[row*VST + tx*8];
        float4 vb = *(const float4*)&Vs[row*VST + tx*8 + 4];
        float v8[8] = {va.x, va.y, va.z, va.w, vb.x, vb.y, vb.z, vb.w};
        float o8[8];
        #pragma unroll
        for (int c = 0; c < 8; ++c)
            o8[c] = a1[r][c] + (v8[c] - mu) * rs * g8[c] + b8[c];
        float* dst = &g_h[(m0 + row)*(size_t)D + tx*8];
        *(float4*)dst       = make_float4(o8[0], o8[1], o8[2], o8[3]);
        *(float4*)(dst + 4) = make_float4(o8[4], o8[5], o8[6], o8[7]);
    }
}

// G2: out = LN(silu(h@linW + linB))
__global__ __launch_bounds__(256) void k_g2(const float* __restrict__ linW,
                                            const float* __restrict__ linB,
                                            const float* __restrict__ lnG,
                                            const float* __restrict__ lnB,
                                            float* __restrict__ out) {
    __shared__ __align__(16) float sm[64*VST];
    __shared__ float mu_s[64], rs_s[64];
    float* As = sm;
    float* Bs = sm + 1280;
    int tid = threadIdx.x;
    int tx = tid & 15;
    int ty = tid >> 4;
    size_t m0 = (size_t)blockIdx.x * 64;

    ull acc[4][4];
    #pragma unroll
    for (int r = 0; r < 4; ++r)
        #pragma unroll
        for (int p = 0; p < 4; ++p) acc[r][p] = 0ull;

    gemm_one(g_h, linW, As, Bs, m0, tid, tx, ty, acc);

    float a2[4][8];
    #pragma unroll
    for (int r = 0; r < 4; ++r)
        #pragma unroll
        for (int p = 0; p < 4; ++p) {
            float2 f = unp2(acc[r][p]);
            a2[r][2*p] = f.x; a2[r][2*p+1] = f.y;
        }

    float bb[8];
    {
        float4 u = *(const float4*)&linB[tx*8];
        float4 v = *(const float4*)&linB[tx*8 + 4];
        bb[0]=u.x; bb[1]=u.y; bb[2]=u.z; bb[3]=u.w; bb[4]=v.x; bb[5]=v.y; bb[6]=v.z; bb[7]=v.w;
    }
    __syncthreads();
    float* Ys = sm;
    #pragma unroll
    for (int r = 0; r < 4; ++r) {
        int row = ty*4 + r;
        #pragma unroll
        for (int c = 0; c < 8; ++c)
            Ys[row*VST + tx*8 + c] = silu_f(a2[r][c] + bb[c]);
    }
    __syncthreads();
    int wid = tid >> 5, lane = tid & 31;
    for (int r = wid; r < 64; r += 8) {
        float s = 0.f, q = 0.f;
        #pragma unroll
        for (int c = lane; c < 128; c += 32) { float v = Ys[r*VST + c]; s += v; q += v*v; }
        #pragma unroll
        for (int o = 16; o > 0; o >>= 1) {
            s += __shfl_down_sync(0xffffffffu, s, o);
            q += __shfl_down_sync(0xffffffffu, q, o);
        }
        if (lane == 0) {
            float mu = s * (1.f/128.f);
            float var = q * (1.f/128.f) - mu*mu;
            mu_s[r] = mu;
            rs_s[r] = rsqrtf(var + 1e-5f);
        }
    }
    __syncthreads();
    float g8[8], b8[8];
    {
        float4 u = *(const float4*)&lnG[tx*8]; float4 v = *(const float4*)&lnG[tx*8+4];
        g8[0]=u.x; g8[1]=u.y; g8[2]=u.z; g8[3]=u.w; g8[4]=v.x; g8[5]=v.y; g8[6]=v.z; g8[7]=v.w;
        u = *(const float4*)&lnB[tx*8]; v = *(const float4*)&lnB[tx*8+4];
        b8[0]=u.x; b8[1]=u.y; b8[2]=u.z; b8[3]=u.w; b8[4]=v.x; b8[5]=v.y; b8[6]=v.z; b8[7]=v.w;
    }
    #pragma unroll
    for (int r = 0; r < 4; ++r) {
        int row = ty*4 + r;
        float mu = mu_s[row], rs = rs_s[row];
        float4 va = *(const float4*)&Ys[row*VST + tx*8];
        float4 vb = *(const float4*)&Ys[row*VST + tx*8 + 4];
        float v8[8] = {va.x, va.y, va.z, va.w, vb.x, vb.y, vb.z, vb.w};
        float o8[8];
        #pragma unroll
        for (int c = 0; c < 8; ++c)
            o8[c] = (v8[c] - mu) * rs * g8[c] + b8[c];
        float* dst = &out[(m0 + row)*(size_t)D + tx*8];
        *(float4*)dst       = make_float4(o8[0], o8[1], o8[2], o8[3]);
        *(float4*)(dst + 4) = make_float4(o8[4], o8[5], o8[6], o8[7]);
    }
}

// ---------------- launch ----------------
extern "C" void kernel_launch(void* const* d_in, const int* in_sizes, int n_in,
                              void* d_out, int out_size) {
    const float* x         = (const float*)d_in[0];
    const int*   edge_rows = (const int*)  d_in[1];
    const int*   edge_cols = (const int*)  d_in[2];
    const float* edge_vals = (const float*)d_in[3];
    const float* sage_W    = (const float*)d_in[4];
    const float* sage_b    = (const float*)d_in[5];
    const float* sage_aggW = (const float*)d_in[6];
    const float* key_W     = (const float*)d_in[7];
    const float* query_W   = (const float*)d_in[8];
    const float* value_W   = (const float*)d_in[9];
    const float* attn_ln_g = (const float*)d_in[10];
    const float* attn_ln_b = (const float*)d_in[11];
    const float* lin_W     = (const float*)d_in[12];
    const float* lin_b     = (const float*)d_in[13];
    const float* ln_g      = (const float*)d_in[14];
    const float* ln_b      = (const float*)d_in[15];
    float* out = (float*)d_out;

    // CSR build
    k_zero_counts<<<(NN + 255)/256, 256>>>();
    k_hist<<<(NE + 255)/256, 256>>>(edge_rows);
    k_scan<<<1, 1024>>>();
    k_scatter<<<(NE + 255)/256, 256>>>(edge_rows, edge_cols, edge_vals);

    // S1 = spmm(x); S2 = spmm(S1) + Xacc epilogue
    k_spmm<<<NN, 128>>>(x, 0);
    k_spmm<<<NN, 128>>>(x, 1);

    // retention weights
    k_weights<<<MROWS/128, 256>>>(x, key_W, query_W);

    // fused sage + value/attn  ->  h
    k_g1<<<MROWS/64, 256>>>(x, sage_W, sage_b, sage_aggW, value_W, attn_ln_g, attn_ln_b);

    // final lin + silu + LN -> out
    k_g2<<<MROWS/64, 256>>>(lin_W, lin_b, ln_g, ln_b, out);
}